// round 1
// baseline (speedup 1.0000x reference)
#include <cuda_runtime.h>
#include <math.h>

// Shapes (fixed by setup_inputs)
#define NAB 4096   // B*Na
#define NA  2048
#define NN  48
#define GG  50
#define GP  52     // padded K for GEMM1 (mult of 4)
#define FF  128
#define RCUT 5.0f

// Scratch (allocation-free rule: __device__ globals)
__device__ float g_Q[NAB*FF];
__device__ float g_K[NAB*FF];
__device__ float g_V[NAB*FF];
__device__ float g_M[NAB*FF];

__device__ __forceinline__ float sspf(float z){
    // softplus(z) - ln2, numerically stable
    float az = fabsf(z);
    return fmaxf(z, 0.f) + log1pf(__expf(-az)) - 0.69314718055994531f;
}

// ---------------------------------------------------------------------------
// Kernel A: Q/K/V = x @ {Wq,Wk,Wv}   (M=4096, N=128, K=128) x3 via gridDim.y
// ---------------------------------------------------------------------------
__global__ void __launch_bounds__(256) qkv_kernel(
    const float* __restrict__ x,
    const float* __restrict__ Wq, const float* __restrict__ Wk,
    const float* __restrict__ Wv)
{
    extern __shared__ float sm[];
    float* sW = sm;              // 128*128
    float* sX = sm + FF*FF;      // 64*128
    const float* Wsrc = (blockIdx.y==0) ? Wq : (blockIdx.y==1 ? Wk : Wv);
    float* outp = (blockIdx.y==0) ? g_Q : (blockIdx.y==1 ? g_K : g_V);
    const int tid = threadIdx.x;
    const int row0 = blockIdx.x * 64;

    for (int i = tid*4; i < FF*FF; i += 1024)
        *(float4*)&sW[i] = *(const float4*)&Wsrc[i];
    for (int i = tid*4; i < 64*FF; i += 1024)
        *(float4*)&sX[i] = *(const float4*)&x[(size_t)row0*FF + i];
    __syncthreads();

    const int tx = tid & 31, ty = tid >> 5;
    const int c0 = tx * 4;
    float acc[8][4];
    #pragma unroll
    for (int m=0;m<8;m++){ acc[m][0]=0.f; acc[m][1]=0.f; acc[m][2]=0.f; acc[m][3]=0.f; }

    for (int k = 0; k < FF; k += 4){
        float bf[4][4];
        #pragma unroll
        for (int kk=0;kk<4;kk++){
            float4 bv = *(float4*)&sW[(k+kk)*FF + c0];
            bf[kk][0]=bv.x; bf[kk][1]=bv.y; bf[kk][2]=bv.z; bf[kk][3]=bv.w;
        }
        #pragma unroll
        for (int m=0;m<8;m++){
            float4 av = *(float4*)&sX[(ty*8+m)*FF + k];
            float af[4] = {av.x, av.y, av.z, av.w};
            #pragma unroll
            for (int kk=0;kk<4;kk++)
                #pragma unroll
                for (int j=0;j<4;j++)
                    acc[m][j] = fmaf(af[kk], bf[kk][j], acc[m][j]);
        }
    }
    #pragma unroll
    for (int m=0;m<8;m++){
        int r = row0 + ty*8 + m;
        *(float4*)&outp[(size_t)r*FF + c0] =
            make_float4(acc[m][0], acc[m][1], acc[m][2], acc[m][3]);
    }
}

// ---------------------------------------------------------------------------
// Kernel B: fused per-atom filter network + masked attention aggregation
// ---------------------------------------------------------------------------
// smem layout (floats)
#define OF_WF1 0
#define OF_WF2 (OF_WF1 + GP*FF)          // 6656
#define OF_BF1 (OF_WF2 + FF*FF)          // 23040
#define OF_BF2 (OF_BF1 + FF)             // 23168
#define OF_G   (OF_BF2 + FF)             // 23296
#define OF_H   (OF_G + NN*GP)            // 25792
#define OF_VG  (OF_H + NN*FF)            // 31936
#define OF_Q   (OF_VG + 49*FF)           // 38208
#define OF_SC  (OF_Q + FF)               // 38336
#define OF_AT  (OF_SC + 64)              // 38400
#define OF_CW  (OF_AT + 64)              // 38464
#define OF_RED (OF_CW + 64)              // 38528
#define OF_NB  (OF_RED + 8*FF)           // 39552 (ints)
#define OF_MK  (OF_NB + 48)              // 39600 (ints)
#define SMB_FLOATS (OF_MK + 48)          // 39648 -> ~155 KB

__global__ void __launch_bounds__(256) mpnn_main(
    const float* __restrict__ r_ij, const int* __restrict__ neighbors,
    const int* __restrict__ pmask, const float* __restrict__ f_ij,
    const float* __restrict__ Wf1, const float* __restrict__ bf1,
    const float* __restrict__ Wf2, const float* __restrict__ bf2,
    float* __restrict__ outW)
{
    extern __shared__ float sm[];
    const int tid  = threadIdx.x;
    const int lane = tid & 31, wid = tid >> 5;
    const int tx = lane, ty = wid;
    const int c0 = tx * 4;

    // Load block-invariant weights once
    for (int i = tid*4; i < GG*FF; i += 1024)
        *(float4*)&sm[OF_WF1 + i] = *(const float4*)&Wf1[i];
    for (int i = GG*FF + tid*4; i < GP*FF; i += 1024)
        *(float4*)&sm[OF_WF1 + i] = make_float4(0.f,0.f,0.f,0.f);
    for (int i = tid*4; i < FF*FF; i += 1024)
        *(float4*)&sm[OF_WF2 + i] = *(const float4*)&Wf2[i];
    if (tid < FF){ sm[OF_BF1+tid] = bf1[tid]; sm[OF_BF2+tid] = bf2[tid]; }
    if (tid < NN){ sm[OF_G + tid*GP + 50] = 0.f; sm[OF_G + tid*GP + 51] = 0.f; }

    int* snb = (int*)&sm[OF_NB];
    int* smk = (int*)&sm[OF_MK];

    for (int atom = blockIdx.x; atom < NAB; atom += gridDim.x){
        __syncthreads();   // protect smem reuse across iterations
        const int b = atom >> 11;               // / NA
        const size_t pbase = (size_t)atom * NN;

        if (tid < NN){
            snb[tid] = neighbors[pbase + tid] + b*NA;
            smk[tid] = pmask[pbase + tid];
            float r = r_ij[pbase + tid];
            sm[OF_CW + tid] = (r < RCUT) ? 0.5f*(__cosf(0.62831853071795865f*r)+1.f) : 0.f;
        }
        if (tid < FF) sm[OF_Q + tid] = g_Q[(size_t)atom*FF + tid];
        {
            const float* fp = f_ij + pbase*GG;
            for (int i = tid; i < NN*GG; i += 256){
                int r = i / GG, c = i - r*GG;
                sm[OF_G + r*GP + c] = 2.f*fp[i] - 1.f;
            }
        }
        __syncthreads();

        // Stage gathered V rows + compute attention scores (gathered K, L2-hit)
        for (int j = wid; j < 49; j += 8){
            int row = (j==0) ? atom : snb[j-1];
            float4 kv = *(const float4*)&g_K[(size_t)row*FF + lane*4];
            float4 vv = *(const float4*)&g_V[(size_t)row*FF + lane*4];
            *(float4*)&sm[OF_VG + j*FF + lane*4] = vv;
            float4 qv = *(const float4*)&sm[OF_Q + lane*4];
            float d = kv.x*qv.x + kv.y*qv.y + kv.z*qv.z + kv.w*qv.w;
            #pragma unroll
            for (int o=16;o;o>>=1) d += __shfl_xor_sync(0xffffffffu, d, o);
            if (lane == 0){
                float s = d * 0.08838834764831845f;   // 1/sqrt(128)
                if (j > 0 && smk[j-1] == 0) s = -1e9f;
                sm[OF_SC + j] = s;
            }
        }
        __syncthreads();

        // Softmax on warp 0 (concurrent with GEMM1 below on other warps)
        if (wid == 0){
            float v0 = (lane      < 49) ? sm[OF_SC + lane]      : -3.4e38f;
            float v1 = (lane + 32 < 49) ? sm[OF_SC + lane + 32] : -3.4e38f;
            float mx = fmaxf(v0, v1);
            #pragma unroll
            for (int o=16;o;o>>=1) mx = fmaxf(mx, __shfl_xor_sync(0xffffffffu, mx, o));
            float e0 = (lane      < 49) ? __expf(v0 - mx) : 0.f;
            float e1 = (lane + 32 < 49) ? __expf(v1 - mx) : 0.f;
            float s = e0 + e1;
            #pragma unroll
            for (int o=16;o;o>>=1) s += __shfl_xor_sync(0xffffffffu, s, o);
            float inv = 1.f / s;
            if (lane      < 49) sm[OF_AT + lane]      = e0 * inv;
            if (lane + 32 < 49) sm[OF_AT + lane + 32] = e1 * inv;
        }

        // GEMM1: h = ssp(g @ Wf1 + bf1), M=48 K=52(pad) N=128
        {
            float acc[6][4];
            #pragma unroll
            for (int m=0;m<6;m++){ acc[m][0]=0.f; acc[m][1]=0.f; acc[m][2]=0.f; acc[m][3]=0.f; }
            #pragma unroll
            for (int k = 0; k < GP; k += 4){
                float bf[4][4];
                #pragma unroll
                for (int kk=0;kk<4;kk++){
                    float4 bv = *(float4*)&sm[OF_WF1 + (k+kk)*FF + c0];
                    bf[kk][0]=bv.x; bf[kk][1]=bv.y; bf[kk][2]=bv.z; bf[kk][3]=bv.w;
                }
                #pragma unroll
                for (int m=0;m<6;m++){
                    float4 av = *(float4*)&sm[OF_G + (ty*6+m)*GP + k];
                    float af[4] = {av.x, av.y, av.z, av.w};
                    #pragma unroll
                    for (int kk=0;kk<4;kk++)
                        #pragma unroll
                        for (int j=0;j<4;j++)
                            acc[m][j] = fmaf(af[kk], bf[kk][j], acc[m][j]);
                }
            }
            float b0 = sm[OF_BF1+c0+0], b1 = sm[OF_BF1+c0+1];
            float b2 = sm[OF_BF1+c0+2], b3 = sm[OF_BF1+c0+3];
            #pragma unroll
            for (int m=0;m<6;m++){
                int r = ty*6 + m;
                float4 hv;
                hv.x = sspf(acc[m][0] + b0);
                hv.y = sspf(acc[m][1] + b1);
                hv.z = sspf(acc[m][2] + b2);
                hv.w = sspf(acc[m][3] + b3);
                *(float4*)&sm[OF_H + r*FF + c0] = hv;
            }
        }
        __syncthreads();

        // GEMM2: W = (h @ Wf2 + bf2) * cutoff ; write W + accumulate attention
        {
            float acc[6][4];
            #pragma unroll
            for (int m=0;m<6;m++){ acc[m][0]=0.f; acc[m][1]=0.f; acc[m][2]=0.f; acc[m][3]=0.f; }
            for (int k = 0; k < FF; k += 4){
                float bf[4][4];
                #pragma unroll
                for (int kk=0;kk<4;kk++){
                    float4 bv = *(float4*)&sm[OF_WF2 + (k+kk)*FF + c0];
                    bf[kk][0]=bv.x; bf[kk][1]=bv.y; bf[kk][2]=bv.z; bf[kk][3]=bv.w;
                }
                #pragma unroll
                for (int m=0;m<6;m++){
                    float4 av = *(float4*)&sm[OF_H + (ty*6+m)*FF + k];
                    float af[4] = {av.x, av.y, av.z, av.w};
                    #pragma unroll
                    for (int kk=0;kk<4;kk++)
                        #pragma unroll
                        for (int j=0;j<4;j++)
                            acc[m][j] = fmaf(af[kk], bf[kk][j], acc[m][j]);
                }
            }
            float b0 = sm[OF_BF2+c0+0], b1 = sm[OF_BF2+c0+1];
            float b2 = sm[OF_BF2+c0+2], b3 = sm[OF_BF2+c0+3];
            float p0=0.f, p1=0.f, p2=0.f, p3=0.f;
            #pragma unroll
            for (int m=0;m<6;m++){
                int r = ty*6 + m;
                float cwv = sm[OF_CW + r];
                float at  = sm[OF_AT + r + 1];
                float4 vg = *(float4*)&sm[OF_VG + (r+1)*FF + c0];
                float w0 = (acc[m][0] + b0) * cwv;
                float w1 = (acc[m][1] + b1) * cwv;
                float w2 = (acc[m][2] + b2) * cwv;
                float w3 = (acc[m][3] + b3) * cwv;
                *(float4*)&outW[((size_t)atom*NN + r)*FF + c0] = make_float4(w0,w1,w2,w3);
                p0 = fmaf(at*vg.x, w0, p0);
                p1 = fmaf(at*vg.y, w1, p1);
                p2 = fmaf(at*vg.z, w2, p2);
                p3 = fmaf(at*vg.w, w3, p3);
            }
            *(float4*)&sm[OF_RED + ty*FF + c0] = make_float4(p0,p1,p2,p3);
        }
        __syncthreads();

        if (tid < FF){
            float msum = sm[OF_AT + 0] * sm[OF_VG + tid];   // self term (unmodulated V)
            #pragma unroll
            for (int t=0;t<8;t++) msum += sm[OF_RED + t*FF + tid];
            g_M[(size_t)atom*FF + tid] = msum;
        }
    }
}

// ---------------------------------------------------------------------------
// Kernel C: out_m = ssp(m @ Wo + bo)
// ---------------------------------------------------------------------------
__global__ void __launch_bounds__(256) out_kernel(
    const float* __restrict__ Wo, const float* __restrict__ bo,
    float* __restrict__ outM)
{
    extern __shared__ float sm[];
    float* sW = sm;
    float* sX = sm + FF*FF;
    const int tid = threadIdx.x;
    const int row0 = blockIdx.x * 64;

    for (int i = tid*4; i < FF*FF; i += 1024)
        *(float4*)&sW[i] = *(const float4*)&Wo[i];
    for (int i = tid*4; i < 64*FF; i += 1024)
        *(float4*)&sX[i] = *(const float4*)&g_M[(size_t)row0*FF + i];
    __syncthreads();

    const int tx = tid & 31, ty = tid >> 5;
    const int c0 = tx * 4;
    float acc[8][4];
    #pragma unroll
    for (int m=0;m<8;m++){ acc[m][0]=0.f; acc[m][1]=0.f; acc[m][2]=0.f; acc[m][3]=0.f; }

    for (int k = 0; k < FF; k += 4){
        float bf[4][4];
        #pragma unroll
        for (int kk=0;kk<4;kk++){
            float4 bv = *(float4*)&sW[(k+kk)*FF + c0];
            bf[kk][0]=bv.x; bf[kk][1]=bv.y; bf[kk][2]=bv.z; bf[kk][3]=bv.w;
        }
        #pragma unroll
        for (int m=0;m<8;m++){
            float4 av = *(float4*)&sX[(ty*8+m)*FF + k];
            float af[4] = {av.x, av.y, av.z, av.w};
            #pragma unroll
            for (int kk=0;kk<4;kk++)
                #pragma unroll
                for (int j=0;j<4;j++)
                    acc[m][j] = fmaf(af[kk], bf[kk][j], acc[m][j]);
        }
    }
    float b0 = bo[c0+0], b1 = bo[c0+1], b2 = bo[c0+2], b3 = bo[c0+3];
    #pragma unroll
    for (int m=0;m<8;m++){
        int r = row0 + ty*8 + m;
        float4 ov;
        ov.x = sspf(acc[m][0] + b0);
        ov.y = sspf(acc[m][1] + b1);
        ov.z = sspf(acc[m][2] + b2);
        ov.w = sspf(acc[m][3] + b3);
        *(float4*)&outM[(size_t)r*FF + c0] = ov;
    }
}

// ---------------------------------------------------------------------------
extern "C" void kernel_launch(void* const* d_in, const int* in_sizes, int n_in,
                              void* d_out, int out_size)
{
    // metadata order: e,x,t,r_ij,neighbors,pairwise_mask,f_ij,Wf1,bf1,Wf2,bf2,Wq,Wk,Wv,Wo,bo
    const float* x         = (const float*)d_in[1];
    const float* r_ij      = (const float*)d_in[3];
    const int*   neighbors = (const int*)  d_in[4];
    const int*   pmask     = (const int*)  d_in[5];
    const float* f_ij      = (const float*)d_in[6];
    const float* Wf1       = (const float*)d_in[7];
    const float* bf1       = (const float*)d_in[8];
    const float* Wf2       = (const float*)d_in[9];
    const float* bf2       = (const float*)d_in[10];
    const float* Wq        = (const float*)d_in[11];
    const float* Wk        = (const float*)d_in[12];
    const float* Wv        = (const float*)d_in[13];
    const float* Wo        = (const float*)d_in[14];
    const float* bo        = (const float*)d_in[15];

    float* out  = (float*)d_out;
    float* outM = out;                          // m: [B,Na,F]
    float* outW = out + (size_t)NAB * FF;       // W: [B,Na,Nn,F]

    size_t smA = (size_t)(FF*FF + 64*FF) * sizeof(float);   // 96 KB
    size_t smB = (size_t)SMB_FLOATS * sizeof(float);        // ~155 KB
    size_t smC = smA;

    cudaFuncSetAttribute(qkv_kernel, cudaFuncAttributeMaxDynamicSharedMemorySize, (int)smA);
    cudaFuncSetAttribute(mpnn_main,  cudaFuncAttributeMaxDynamicSharedMemorySize, (int)smB);
    cudaFuncSetAttribute(out_kernel, cudaFuncAttributeMaxDynamicSharedMemorySize, (int)smC);

    qkv_kernel<<<dim3(NAB/64, 3), 256, smA>>>(x, Wq, Wk, Wv);
    mpnn_main<<<152, 256, smB>>>(r_ij, neighbors, pmask, f_ij,
                                 Wf1, bf1, Wf2, bf2, outW);
    out_kernel<<<NAB/64, 256, smC>>>(Wo, bo, outM);
}

// round 3
// speedup vs baseline: 1.7331x; 1.7331x over previous
#include <cuda_runtime.h>
#include <cuda_bf16.h>
#include <cstdint>
#include <math.h>

#define NAB 4096
#define NA  2048
#define NN  48
#define FF  128
#define NPAIR (NAB*NN)       // 196608
#define NTILES (NPAIR/128)   // 1536
#define RCUT 5.0f

#define KP1 72    // padded K stride (bf16 elems) for GEMM1 (K=64)
#define KP2 136   // padded K stride for GEMM2 (K=128)

// dynamic smem byte offsets
#define SM_GHI  0
#define SM_GLO  18432
#define SM_HHI  36864
#define SM_HLO  71680
#define SM_B1HI 106496
#define SM_B1LO 124928
#define SM_B2HI 143360
#define SM_B2LO 178176
#define SM_TOT  212992

// Scratch (__device__ globals; no allocations allowed)
__device__ float g_Q[NAB*FF];
__device__ float g_K[NAB*FF];
__device__ float g_V[NAB*FF];
__device__ float g_M[NAB*FF];

// ---------------------------------------------------------------------------
__device__ __forceinline__ float sspf(float z){
    float az = fabsf(z);
    float e = __expf(-az);
    return fmaxf(z, 0.f) + __logf(1.f + e) - 0.69314718055994531f;
}

// split a pair of floats into packed bf16x2 hi and lo words
__device__ __forceinline__ void split2(float a, float b, uint32_t &hi, uint32_t &lo){
    __nv_bfloat16 ah = __float2bfloat16(a);
    __nv_bfloat16 bh = __float2bfloat16(b);
    __nv_bfloat16 al = __float2bfloat16(a - __bfloat162float(ah));
    __nv_bfloat16 bl = __float2bfloat16(b - __bfloat162float(bh));
    hi = ((uint32_t)__bfloat16_as_ushort(bh) << 16) | (uint32_t)__bfloat16_as_ushort(ah);
    lo = ((uint32_t)__bfloat16_as_ushort(bl) << 16) | (uint32_t)__bfloat16_as_ushort(al);
}

__device__ __forceinline__ void mma_bf16(float* c, const uint32_t* a, const uint32_t* b){
    asm volatile(
        "mma.sync.aligned.m16n8k16.row.col.f32.bf16.bf16.f32 "
        "{%0,%1,%2,%3}, {%4,%5,%6,%7}, {%8,%9}, {%0,%1,%2,%3};"
        : "+f"(c[0]), "+f"(c[1]), "+f"(c[2]), "+f"(c[3])
        : "r"(a[0]), "r"(a[1]), "r"(a[2]), "r"(a[3]), "r"(b[0]), "r"(b[1]));
}

// bf16x3 GEMM: acc += Ahi@Bhi + Ahi@Blo + Alo@Bhi  (warp tile 64x32)
template<int KSTEPS, int KPAD>
__device__ __forceinline__ void gemm_bf16x3(
    const __nv_bfloat16* __restrict__ Ahi, const __nv_bfloat16* __restrict__ Alo,
    const __nv_bfloat16* __restrict__ Bhi, const __nv_bfloat16* __restrict__ Blo,
    int m0, int n0, int lane, float acc[4][4][4])
{
    const int ar = m0 + (lane >> 2);
    const int ac = (lane & 3) * 2;
    const int bn = n0 + (lane >> 2);

    #pragma unroll
    for (int ks = 0; ks < KSTEPS; ks++){
        const int k0 = ks * 16;
        uint32_t ahi[4][4], alo[4][4], bhi[4][2], blo[4][2];
        #pragma unroll
        for (int mf = 0; mf < 4; mf++){
            const __nv_bfloat16* p = Ahi + (ar + mf*16)*KPAD + ac + k0;
            const __nv_bfloat16* q = Alo + (ar + mf*16)*KPAD + ac + k0;
            ahi[mf][0] = *(const uint32_t*)(p);
            ahi[mf][1] = *(const uint32_t*)(p + 8*KPAD);
            ahi[mf][2] = *(const uint32_t*)(p + 8);
            ahi[mf][3] = *(const uint32_t*)(p + 8*KPAD + 8);
            alo[mf][0] = *(const uint32_t*)(q);
            alo[mf][1] = *(const uint32_t*)(q + 8*KPAD);
            alo[mf][2] = *(const uint32_t*)(q + 8);
            alo[mf][3] = *(const uint32_t*)(q + 8*KPAD + 8);
        }
        #pragma unroll
        for (int nf = 0; nf < 4; nf++){
            const __nv_bfloat16* p = Bhi + (bn + nf*8)*KPAD + ac + k0;
            const __nv_bfloat16* q = Blo + (bn + nf*8)*KPAD + ac + k0;
            bhi[nf][0] = *(const uint32_t*)(p);
            bhi[nf][1] = *(const uint32_t*)(p + 8);
            blo[nf][0] = *(const uint32_t*)(q);
            blo[nf][1] = *(const uint32_t*)(q + 8);
        }
        #pragma unroll
        for (int mf = 0; mf < 4; mf++)
            #pragma unroll
            for (int nf = 0; nf < 4; nf++){
                mma_bf16(acc[mf][nf], ahi[mf], bhi[nf]);
                mma_bf16(acc[mf][nf], ahi[mf], blo[nf]);
                mma_bf16(acc[mf][nf], alo[mf], bhi[nf]);
            }
    }
}

// ---------------------------------------------------------------------------
// Persistent fused filter network on HMMA (bf16x3)
// ---------------------------------------------------------------------------
__global__ void __launch_bounds__(256,1) filter_kernel(
    const float* __restrict__ f_ij, const float* __restrict__ r_ij,
    const float* __restrict__ Wf1, const float* __restrict__ bf1,
    const float* __restrict__ Wf2, const float* __restrict__ bf2,
    float* __restrict__ outW)
{
    extern __shared__ char dynsm[];
    __shared__ float s_cw[128], s_bf1[128], s_bf2[128];

    __nv_bfloat16* Ghi  = (__nv_bfloat16*)(dynsm + SM_GHI);
    __nv_bfloat16* Glo  = (__nv_bfloat16*)(dynsm + SM_GLO);
    __nv_bfloat16* Hhi  = (__nv_bfloat16*)(dynsm + SM_HHI);
    __nv_bfloat16* Hlo  = (__nv_bfloat16*)(dynsm + SM_HLO);
    __nv_bfloat16* B1hi = (__nv_bfloat16*)(dynsm + SM_B1HI);
    __nv_bfloat16* B1lo = (__nv_bfloat16*)(dynsm + SM_B1LO);
    __nv_bfloat16* B2hi = (__nv_bfloat16*)(dynsm + SM_B2HI);
    __nv_bfloat16* B2lo = (__nv_bfloat16*)(dynsm + SM_B2LO);

    const int tid  = threadIdx.x;
    const int lane = tid & 31, wid = tid >> 5;
    const int m0 = (wid & 1) * 64;
    const int n0 = (wid >> 1) * 32;

    // ---- load + transpose + split weights once (persistent block) ----
    for (int i = tid; i < 128*32; i += 256){
        int n = i >> 5, kp = i & 31, k0 = kp*2;
        float v0 = (k0   < 50) ? Wf1[k0*FF + n]     : 0.f;
        float v1 = (k0+1 < 50) ? Wf1[(k0+1)*FF + n] : 0.f;
        uint32_t hi, lo; split2(v0, v1, hi, lo);
        *(uint32_t*)(B1hi + n*KP1 + k0) = hi;
        *(uint32_t*)(B1lo + n*KP1 + k0) = lo;
    }
    for (int i = tid; i < 128*64; i += 256){
        int n = i >> 6, kp = i & 63, k0 = kp*2;
        float v0 = Wf2[k0*FF + n];
        float v1 = Wf2[(k0+1)*FF + n];
        uint32_t hi, lo; split2(v0, v1, hi, lo);
        *(uint32_t*)(B2hi + n*KP2 + k0) = hi;
        *(uint32_t*)(B2lo + n*KP2 + k0) = lo;
    }
    if (tid < 128){ s_bf1[tid] = bf1[tid]; s_bf2[tid] = bf2[tid]; }
    __syncthreads();

    for (int t = blockIdx.x; t < NTILES; t += gridDim.x){
        const int tb = t * 128;
        __syncthreads();   // protect s_cw / G from previous iteration readers

        // ---- load A1 tile: G = 2*f_ij - 1, split hi/lo ----
        for (int i = tid; i < 128*32; i += 256){
            int row = i >> 5, kp = i & 31, k0 = kp*2;
            const float* fp = f_ij + (size_t)(tb + row)*50;
            float g0 = (k0   < 50) ? 2.f*fp[k0]   - 1.f : 0.f;
            float g1 = (k0+1 < 50) ? 2.f*fp[k0+1] - 1.f : 0.f;
            uint32_t hi, lo; split2(g0, g1, hi, lo);
            *(uint32_t*)(Ghi + row*KP1 + k0) = hi;
            *(uint32_t*)(Glo + row*KP1 + k0) = lo;
        }
        if (tid < 128){
            float r = r_ij[tb + tid];
            s_cw[tid] = (r < RCUT) ? 0.5f*(__cosf(0.62831853071795865f*r) + 1.f) : 0.f;
        }
        __syncthreads();

        // ---- GEMM1: D1 = G @ Wf1^T(stored [n][k]) ----
        float acc[4][4][4];
        #pragma unroll
        for (int mf=0;mf<4;mf++)
            #pragma unroll
            for (int nf=0;nf<4;nf++)
                #pragma unroll
                for (int u=0;u<4;u++) acc[mf][nf][u] = 0.f;
        gemm_bf16x3<4, KP1>(Ghi, Glo, B1hi, B1lo, m0, n0, lane, acc);

        // ---- epilogue 1: H = ssp(D1 + bf1) -> split bf16 into smem ----
        {
            const int r  = m0 + (lane >> 2);
            const int cc = n0 + (lane & 3)*2;
            #pragma unroll
            for (int mf = 0; mf < 4; mf++){
                #pragma unroll
                for (int nf = 0; nf < 4; nf++){
                    int rr = r + mf*16, c = cc + nf*8;
                    float b0 = s_bf1[c], b1 = s_bf1[c+1];
                    uint32_t hi, lo;
                    split2(sspf(acc[mf][nf][0] + b0), sspf(acc[mf][nf][1] + b1), hi, lo);
                    *(uint32_t*)(Hhi + rr*KP2 + c) = hi;
                    *(uint32_t*)(Hlo + rr*KP2 + c) = lo;
                    split2(sspf(acc[mf][nf][2] + b0), sspf(acc[mf][nf][3] + b1), hi, lo);
                    *(uint32_t*)(Hhi + (rr+8)*KP2 + c) = hi;
                    *(uint32_t*)(Hlo + (rr+8)*KP2 + c) = lo;
                }
            }
        }
        __syncthreads();

        // ---- GEMM2: D2 = H @ Wf2^T ----
        #pragma unroll
        for (int mf=0;mf<4;mf++)
            #pragma unroll
            for (int nf=0;nf<4;nf++)
                #pragma unroll
                for (int u=0;u<4;u++) acc[mf][nf][u] = 0.f;
        gemm_bf16x3<8, KP2>(Hhi, Hlo, B2hi, B2lo, m0, n0, lane, acc);

        // ---- epilogue 2: W = (D2 + bf2) * cutoff, direct global store ----
        {
            const int r  = m0 + (lane >> 2);
            const int cc = n0 + (lane & 3)*2;
            #pragma unroll
            for (int mf = 0; mf < 4; mf++){
                int rr = r + mf*16;
                float cw0 = s_cw[rr], cw1 = s_cw[rr+8];
                #pragma unroll
                for (int nf = 0; nf < 4; nf++){
                    int c = cc + nf*8;
                    float b0 = s_bf2[c], b1 = s_bf2[c+1];
                    float2 o0, o1;
                    o0.x = (acc[mf][nf][0] + b0) * cw0;
                    o0.y = (acc[mf][nf][1] + b1) * cw0;
                    o1.x = (acc[mf][nf][2] + b0) * cw1;
                    o1.y = (acc[mf][nf][3] + b1) * cw1;
                    *(float2*)&outW[((size_t)(tb + rr))*FF + c]     = o0;
                    *(float2*)&outW[((size_t)(tb + rr + 8))*FF + c] = o1;
                }
            }
        }
    }
}

// ---------------------------------------------------------------------------
// QKV: x @ {Wq,Wk,Wv}, 32-row tiles
// ---------------------------------------------------------------------------
__global__ void __launch_bounds__(256) qkv_kernel(
    const float* __restrict__ x,
    const float* __restrict__ Wq, const float* __restrict__ Wk, const float* __restrict__ Wv)
{
    extern __shared__ char dynsm[];
    float* sW = (float*)dynsm;
    float* sX = sW + FF*FF;
    const float* Wsrc = (blockIdx.y == 0) ? Wq : (blockIdx.y == 1 ? Wk : Wv);
    float* outp = (blockIdx.y == 0) ? g_Q : (blockIdx.y == 1 ? g_K : g_V);
    const int tid = threadIdx.x;
    const int row0 = blockIdx.x * 32;

    for (int i = tid*4; i < FF*FF; i += 1024) *(float4*)&sW[i] = *(const float4*)&Wsrc[i];
    for (int i = tid*4; i < 32*FF; i += 1024) *(float4*)&sX[i] = *(const float4*)&x[(size_t)row0*FF + i];
    __syncthreads();

    const int lane = tid & 31, wd = tid >> 5;
    const int c0 = lane * 4;
    float acc[4][4];
    #pragma unroll
    for (int m=0;m<4;m++){ acc[m][0]=0.f; acc[m][1]=0.f; acc[m][2]=0.f; acc[m][3]=0.f; }

    for (int k = 0; k < FF; k += 4){
        float bf[4][4];
        #pragma unroll
        for (int kk=0;kk<4;kk++){
            float4 bv = *(float4*)&sW[(k+kk)*FF + c0];
            bf[kk][0]=bv.x; bf[kk][1]=bv.y; bf[kk][2]=bv.z; bf[kk][3]=bv.w;
        }
        #pragma unroll
        for (int m=0;m<4;m++){
            float4 av = *(float4*)&sX[(wd*4+m)*FF + k];
            float af[4] = {av.x, av.y, av.z, av.w};
            #pragma unroll
            for (int kk=0;kk<4;kk++)
                #pragma unroll
                for (int j=0;j<4;j++)
                    acc[m][j] = fmaf(af[kk], bf[kk][j], acc[m][j]);
        }
    }
    #pragma unroll
    for (int m=0;m<4;m++){
        int r = row0 + wd*4 + m;
        *(float4*)&outp[(size_t)r*FF + c0] = make_float4(acc[m][0], acc[m][1], acc[m][2], acc[m][3]);
    }
}

// ---------------------------------------------------------------------------
// Attention aggregation
// ---------------------------------------------------------------------------
__global__ void __launch_bounds__(128) attn_kernel(
    const int* __restrict__ neighbors, const int* __restrict__ pmask,
    const float* __restrict__ W)
{
    __shared__ float s_q[128];
    __shared__ float s_sc[64];
    __shared__ float s_at[64];
    __shared__ int s_nb[48];
    __shared__ int s_mk[48];
    const int atom = blockIdx.x;
    const int tid = threadIdx.x, lane = tid & 31, wd = tid >> 5;

    s_q[tid] = g_Q[(size_t)atom*FF + tid];
    if (tid < NN){
        s_nb[tid] = neighbors[atom*NN + tid] + (atom >> 11)*NA;
        s_mk[tid] = pmask[atom*NN + tid];
    }
    __syncthreads();

    for (int j = wd; j < 49; j += 4){
        int row = j ? s_nb[j-1] : atom;
        float4 kv = *(const float4*)&g_K[(size_t)row*FF + lane*4];
        float4 qv = *(const float4*)&s_q[lane*4];
        float d = kv.x*qv.x + kv.y*qv.y + kv.z*qv.z + kv.w*qv.w;
        #pragma unroll
        for (int o=16;o;o>>=1) d += __shfl_xor_sync(0xffffffffu, d, o);
        if (lane == 0){
            float s = d * 0.08838834764831845f;  // 1/sqrt(128)
            if (j > 0 && s_mk[j-1] == 0) s = -1e9f;
            s_sc[j] = s;
        }
    }
    __syncthreads();

    if (wd == 0){
        float v0 = (lane      < 49) ? s_sc[lane]      : -3.4e38f;
        float v1 = (lane + 32 < 49) ? s_sc[lane + 32] : -3.4e38f;
        float mx = fmaxf(v0, v1);
        #pragma unroll
        for (int o=16;o;o>>=1) mx = fmaxf(mx, __shfl_xor_sync(0xffffffffu, mx, o));
        float e0 = (lane      < 49) ? __expf(v0 - mx) : 0.f;
        float e1 = (lane + 32 < 49) ? __expf(v1 - mx) : 0.f;
        float s = e0 + e1;
        #pragma unroll
        for (int o=16;o;o>>=1) s += __shfl_xor_sync(0xffffffffu, s, o);
        float inv = 1.f / s;
        if (lane      < 49) s_at[lane]      = e0 * inv;
        if (lane + 32 < 49) s_at[lane + 32] = e1 * inv;
    }
    __syncthreads();

    float acc = s_at[0] * g_V[(size_t)atom*FF + tid];
    const float* wrow = W + (size_t)atom*NN*FF + tid;
    #pragma unroll 4
    for (int j = 0; j < NN; j++)
        acc += s_at[j+1] * g_V[(size_t)s_nb[j]*FF + tid] * wrow[(size_t)j*FF];
    g_M[(size_t)atom*FF + tid] = acc;
}

// ---------------------------------------------------------------------------
// Output projection
// ---------------------------------------------------------------------------
__global__ void __launch_bounds__(256) out_kernel(
    const float* __restrict__ Wo, const float* __restrict__ bo,
    float* __restrict__ outM)
{
    extern __shared__ char dynsm[];
    float* sW = (float*)dynsm;
    float* sX = sW + FF*FF;
    const int tid = threadIdx.x;
    const int row0 = blockIdx.x * 32;

    for (int i = tid*4; i < FF*FF; i += 1024) *(float4*)&sW[i] = *(const float4*)&Wo[i];
    for (int i = tid*4; i < 32*FF; i += 1024) *(float4*)&sX[i] = *(const float4*)&g_M[(size_t)row0*FF + i];
    __syncthreads();

    const int lane = tid & 31, wd = tid >> 5;
    const int c0 = lane * 4;
    float acc[4][4];
    #pragma unroll
    for (int m=0;m<4;m++){ acc[m][0]=0.f; acc[m][1]=0.f; acc[m][2]=0.f; acc[m][3]=0.f; }

    for (int k = 0; k < FF; k += 4){
        float bf[4][4];
        #pragma unroll
        for (int kk=0;kk<4;kk++){
            float4 bv = *(float4*)&sW[(k+kk)*FF + c0];
            bf[kk][0]=bv.x; bf[kk][1]=bv.y; bf[kk][2]=bv.z; bf[kk][3]=bv.w;
        }
        #pragma unroll
        for (int m=0;m<4;m++){
            float4 av = *(float4*)&sX[(wd*4+m)*FF + k];
            float af[4] = {av.x, av.y, av.z, av.w};
            #pragma unroll
            for (int kk=0;kk<4;kk++)
                #pragma unroll
                for (int j=0;j<4;j++)
                    acc[m][j] = fmaf(af[kk], bf[kk][j], acc[m][j]);
        }
    }
    float b0 = bo[c0+0], b1 = bo[c0+1], b2 = bo[c0+2], b3 = bo[c0+3];
    #pragma unroll
    for (int m=0;m<4;m++){
        int r = row0 + wd*4 + m;
        float4 ov;
        ov.x = sspf(acc[m][0] + b0);
        ov.y = sspf(acc[m][1] + b1);
        ov.z = sspf(acc[m][2] + b2);
        ov.w = sspf(acc[m][3] + b3);
        *(float4*)&outM[(size_t)r*FF + c0] = ov;
    }
}

// ---------------------------------------------------------------------------
extern "C" void kernel_launch(void* const* d_in, const int* in_sizes, int n_in,
                              void* d_out, int out_size)
{
    // order: e,x,t,r_ij,neighbors,pairwise_mask,f_ij,Wf1,bf1,Wf2,bf2,Wq,Wk,Wv,Wo,bo
    const float* x         = (const float*)d_in[1];
    const float* r_ij      = (const float*)d_in[3];
    const int*   neighbors = (const int*)  d_in[4];
    const int*   pmask     = (const int*)  d_in[5];
    const float* f_ij      = (const float*)d_in[6];
    const float* Wf1       = (const float*)d_in[7];
    const float* bf1       = (const float*)d_in[8];
    const float* Wf2       = (const float*)d_in[9];
    const float* bf2       = (const float*)d_in[10];
    const float* Wq        = (const float*)d_in[11];
    const float* Wk        = (const float*)d_in[12];
    const float* Wv        = (const float*)d_in[13];
    const float* Wo        = (const float*)d_in[14];
    const float* bo        = (const float*)d_in[15];

    float* out  = (float*)d_out;
    float* outM = out;                        // m: [B,Na,F]
    float* outW = out + (size_t)NAB * FF;     // W: [B,Na,Nn,F]

    size_t smG = (size_t)(FF*FF + 32*FF) * sizeof(float);   // 80 KB
    size_t smF = SM_TOT;                                    // 208 KB

    cudaFuncSetAttribute(qkv_kernel,    cudaFuncAttributeMaxDynamicSharedMemorySize, (int)smG);
    cudaFuncSetAttribute(filter_kernel, cudaFuncAttributeMaxDynamicSharedMemorySize, (int)smF);
    cudaFuncSetAttribute(out_kernel,    cudaFuncAttributeMaxDynamicSharedMemorySize, (int)smG);

    qkv_kernel<<<dim3(NAB/32, 3), 256, smG>>>(x, Wq, Wk, Wv);
    filter_kernel<<<152, 256, smF>>>(f_ij, r_ij, Wf1, bf1, Wf2, bf2, outW);
    attn_kernel<<<NAB, 128>>>(neighbors, pmask, outW);
    out_kernel<<<NAB/32, 256, smG>>>(Wo, bo, outM);
}